// round 17
// baseline (speedup 1.0000x reference)
#include <cuda_runtime.h>
#include <cuda_fp16.h>
#include <stdint.h>
#include <math.h>

#define Nn 4
#define Kk 1024
#define Mm 1024
#define Hh 16
#define Dd 64
#define Ff 4096
#define NK 4096   // Nn*Kk

typedef __half hf;

// ---------------- scratch (no allocations allowed) ----------------
__device__ float g_x[NK * Mm];
__device__ float g_y[NK * Mm];
__device__ float g_z[NK * Mm];
__device__ float g_b3[3 * Mm];
__device__ float g_b2[2 * Mm];

__device__ __align__(256) hf g_d[NK * Mm];          // dec fp16
__device__ __align__(256) hf g_e[NK * Mm];          // enc fp16
__device__ __align__(256) hf g_yh[NK * Mm];         // ln1 out fp16
__device__ __align__(256) hf g_zh[NK * Mm];         // ln2 out fp16
__device__ __align__(256) hf g_a[NK * Mm];          // attn out fp16
__device__ __align__(256) hf g_h[NK * Ff];          // ffn hidden fp16
__device__ __align__(256) hf g_qkv[NK * 3 * Mm];    // fused qkv
__device__ __align__(256) hf g_kv[NK * 2 * Mm];     // fused cross kv
__device__ __align__(256) hf g_q[NK * Mm];          // cross q
__device__ __align__(256) hf g_w[16 * 1024 * 1024]; // transposed weights fp16

// weight offsets (elements) in g_w
#define WOFF_QS (0 * 1048576)
#define WOFF_KS (1 * 1048576)
#define WOFF_VS (2 * 1048576)
#define WOFF_QC (3 * 1048576)
#define WOFF_KC (4 * 1048576)
#define WOFF_VC (5 * 1048576)
#define WOFF_OS (6 * 1048576)
#define WOFF_OC (7 * 1048576)
#define WOFF_W1 (8 * 1048576)
#define WOFF_W2 (12 * 1048576)

// ---------------- PTX helpers ----------------
__device__ __forceinline__ uint32_t smem_u32(const void* p) {
    uint32_t a;
    asm("{ .reg .u64 t; cvta.to.shared.u64 t, %1; cvt.u32.u64 %0, t; }" : "=r"(a) : "l"(p));
    return a;
}

__device__ __forceinline__ void cp16(uint32_t s, const void* g) {
    asm volatile("cp.async.cg.shared.global [%0], [%1], 16;" :: "r"(s), "l"(g));
}

__device__ __forceinline__ void ldm4(uint32_t* r, uint32_t addr) {
    asm volatile("ldmatrix.sync.aligned.m8n8.x4.shared.b16 {%0,%1,%2,%3}, [%4];"
                 : "=r"(r[0]), "=r"(r[1]), "=r"(r[2]), "=r"(r[3]) : "r"(addr));
}

__device__ __forceinline__ void ldm4t(uint32_t* r, uint32_t addr) {
    asm volatile("ldmatrix.sync.aligned.m8n8.x4.trans.shared.b16 {%0,%1,%2,%3}, [%4];"
                 : "=r"(r[0]), "=r"(r[1]), "=r"(r[2]), "=r"(r[3]) : "r"(addr));
}

__device__ __forceinline__ void mma16816(float* c, const uint32_t* a, const uint32_t* b) {
    asm volatile(
        "mma.sync.aligned.m16n8k16.row.col.f32.f16.f16.f32 "
        "{%0,%1,%2,%3}, {%4,%5,%6,%7}, {%8,%9}, {%0,%1,%2,%3};"
        : "+f"(c[0]), "+f"(c[1]), "+f"(c[2]), "+f"(c[3])
        : "r"(a[0]), "r"(a[1]), "r"(a[2]), "r"(a[3]), "r"(b[0]), "r"(b[1]));
}

// pack two f32 -> f16x2: lower half = first arg
__device__ __forceinline__ uint32_t packhf(float lo, float hi) {
    uint32_t r;
    asm("cvt.rn.f16x2.f32 %0, %1, %2;" : "=r"(r) : "f"(hi), "f"(lo));
    return r;
}

// ---------------- tensor-core GEMM: C[I,J] = A[I,Kd] @ B^T  (single fp16) ----------------
// Tile 128x128, 256 thr (8 warps, 2m x 4n, warp tile 64x32), BK=64, 3-stage,
// 144B row stride (conflict-free ldmatrix). 2 CTAs/SM via launch_bounds.
#define G_ROWB 144
#define G_AB (128 * G_ROWB)             // 18432
#define G_STAGE (2 * G_AB)              // 36864 (A + B)
#define GSM_SIZE (3 * G_STAGE)          // 110592

__global__ __launch_bounds__(256, 2) void gemm_tc(
    const hf* __restrict__ A, const hf* __restrict__ B,
    const float* __restrict__ bias, const float* __restrict__ res,
    float* __restrict__ Cf, hf* __restrict__ Ch,
    int Kd, int J, int relu)
{
    extern __shared__ char smem[];
    uint32_t sb = smem_u32(smem);
    int tid = threadIdx.x;
    int wid = tid >> 5, lane = tid & 31;
    int wm = wid >> 2, wn = wid & 3;            // warp grid 2 (M) x 4 (N)
    int i0 = blockIdx.y << 7, j0 = blockIdx.x << 7;

    size_t rowBytes = (size_t)Kd * 2;
    const char* gpA = (const char*)(A + (size_t)i0 * Kd);
    const char* gpB = (const char*)(B + (size_t)j0 * Kd);

    // per stage: A 128 rows x 8 cols of 16B (BK=64 -> 128B/row); same for B
    auto load_stage = [&](int s, int k0) {
        uint32_t base = sb + (s % 3) * G_STAGE;
        size_t gk = (size_t)k0 * 2;
        #pragma unroll
        for (int c = 0; c < 8; c++) {
            int idx = c * 256 + tid;
            if (c < 4) {
                int row = idx >> 3, col = idx & 7;
                cp16(base + row * G_ROWB + col * 16,
                     gpA + (size_t)row * rowBytes + gk + col * 16);
            } else {
                int i2 = idx - 1024;
                int row = i2 >> 3, col = i2 & 7;
                cp16(base + G_AB + row * G_ROWB + col * 16,
                     gpB + (size_t)row * rowBytes + gk + col * 16);
            }
        }
        asm volatile("cp.async.commit_group;" ::: "memory");
    };

    float acc[4][4][4] = {};

    int aRow = wm * 64 + (lane & 7) + ((lane >> 3) & 1) * 8;
    int aByte = ((lane >> 4) & 1) * 16;
    int bRow = wn * 32 + (lane & 7) + ((lane >> 4) & 1) * 8;
    int bByte = ((lane >> 3) & 1) * 16;

    int S = Kd >> 6;
    load_stage(0, 0);
    load_stage(1, 64);

    for (int s = 0; s < S; s++) {
        if (s + 2 < S) {
            load_stage(s + 2, (s + 2) << 6);
            asm volatile("cp.async.wait_group 2;" ::: "memory");
        } else if (s + 1 < S) {
            asm volatile("cp.async.wait_group 1;" ::: "memory");
        } else {
            asm volatile("cp.async.wait_group 0;" ::: "memory");
        }
        __syncthreads();

        uint32_t stb = sb + (s % 3) * G_STAGE;

        #pragma unroll
        for (int ks = 0; ks < 4; ks++) {
            uint32_t ah[4][4];
            #pragma unroll
            for (int fm = 0; fm < 4; fm++) {
                uint32_t off = (uint32_t)(aRow + fm * 16) * G_ROWB + ks * 32 + aByte;
                ldm4(ah[fm], stb + off);
            }
            #pragma unroll
            for (int p = 0; p < 2; p++) {
                uint32_t off = (uint32_t)(bRow + p * 16) * G_ROWB + ks * 32 + bByte;
                uint32_t tb[4];
                ldm4(tb, stb + G_AB + off);
                #pragma unroll
                for (int fm = 0; fm < 4; fm++) {
                    mma16816(acc[fm][2 * p],     ah[fm], tb);
                    mma16816(acc[fm][2 * p + 1], ah[fm], tb + 2);
                }
            }
        }
        __syncthreads();
    }

    bool hb = bias != nullptr, hr = res != nullptr, hf_ = Cf != nullptr, hh = Ch != nullptr;
    int g = lane >> 2, q = lane & 3;
    #pragma unroll
    for (int fm = 0; fm < 4; fm++) {
        #pragma unroll
        for (int fn = 0; fn < 4; fn++) {
            int col = j0 + wn * 32 + fn * 8 + q * 2;
            #pragma unroll
            for (int half = 0; half < 2; half++) {
                int row = i0 + wm * 64 + fm * 16 + g + half * 8;
                size_t base = (size_t)row * J + col;
                float v0 = acc[fm][fn][half * 2 + 0];
                float v1 = acc[fm][fn][half * 2 + 1];
                if (hb) { v0 += bias[col]; v1 += bias[col + 1]; }
                if (hr) { v0 += res[base]; v1 += res[base + 1]; }
                if (relu) { v0 = fmaxf(v0, 0.f); v1 = fmaxf(v1, 0.f); }
                if (hf_) { Cf[base] = v0; Cf[base + 1] = v1; }
                if (hh)  { *(uint32_t*)(Ch + base) = packhf(v0, v1); }
            }
        }
    }
}

// ---------------- tensor-core flash attention (single fp16, strided layouts) ----------------
#define AROWB 144
#define AQ_BYTES (128 * AROWB)          // 18432
#define AKV_BYTES (64 * AROWB)          // 9216
#define ASTAGE (2 * AKV_BYTES)          // 18432: K, V
#define ATTN_SMEM2 (AQ_BYTES + 2 * ASTAGE)   // 55296

__global__ __launch_bounds__(256) void attn_tc(
    const hf* __restrict__ Q, const hf* __restrict__ Kp, const hf* __restrict__ Vp,
    int ldq, int ldkv,
    int causal, hf* __restrict__ O)
{
    extern __shared__ char smem[];
    uint32_t sb = smem_u32(smem);
    int tid = threadIdx.x, lane = tid & 31, wm = tid >> 5;
    int g = lane >> 2, qd = lane & 3;
    int nh = blockIdx.y;
    int n = nh >> 4, h = nh & 15;
    int q0 = blockIdx.x << 7;

    uint32_t sQ = sb;
    uint32_t sKV0 = sb + AQ_BYTES;

    const char* kvptr[2] = {(const char*)Kp, (const char*)Vp};
    size_t qOff0  = ((size_t)n * Kk) * ldq  + (size_t)h * Dd;
    size_t kvOff0 = ((size_t)n * Kk) * ldkv + (size_t)h * Dd;

    #pragma unroll
    for (int c = 0; c < 4; c++) {
        int idx = c * 256 + tid;
        int row = idx >> 3, col = idx & 7;
        cp16(sQ + row * AROWB + col * 16,
             (const char*)Q + (qOff0 + (size_t)(q0 + row) * ldq) * 2 + col * 16);
    }

    auto load_kv = [&](int s, int l0) {
        uint32_t base = sKV0 + (s & 1) * ASTAGE;
        #pragma unroll
        for (int c = 0; c < 4; c++) {
            int idx = c * 256 + tid;
            int arr = idx >> 9, rem = idx & 511, row = rem >> 3, col = rem & 7;
            cp16(base + arr * AKV_BYTES + row * AROWB + col * 16,
                 kvptr[arr] + (kvOff0 + (size_t)(l0 + row) * ldkv) * 2 + col * 16);
        }
        asm volatile("cp.async.commit_group;" ::: "memory");
    };
    load_kv(0, 0);

    int nt = causal ? ((q0 + 128) >> 6) : (Kk >> 6);

    int aRow = (lane & 7) + ((lane >> 3) & 1) * 8;
    int aByte = ((lane >> 4) & 1) * 16;
    int bRow = (lane & 7) + ((lane >> 4) & 1) * 8;
    int bByte = ((lane >> 3) & 1) * 16;
    int vRow = lane & 15;
    int vByte = ((lane >> 4) & 1) * 16;

    uint32_t qf[4][4];
    float Oacc[8][4] = {};
    float mrow[2] = {-1e30f, -1e30f};
    float lrow[2] = {0.f, 0.f};
    const float scale = 0.125f;

    for (int t = 0; t < nt; t++) {
        if (t + 1 < nt) {
            load_kv(t + 1, (t + 1) << 6);
            asm volatile("cp.async.wait_group 1;" ::: "memory");
        } else {
            asm volatile("cp.async.wait_group 0;" ::: "memory");
        }
        __syncthreads();

        if (t == 0) {
            #pragma unroll
            for (int kc = 0; kc < 4; kc++)
                ldm4(qf[kc], sQ + (uint32_t)(wm * 16 + aRow) * AROWB + kc * 32 + aByte);
        }

        uint32_t kb = sKV0 + (t & 1) * ASTAGE;
        int l0 = t << 6;

        float S[8][4] = {};
        #pragma unroll
        for (int kc = 0; kc < 4; kc++) {
            #pragma unroll
            for (int p = 0; p < 4; p++) {
                uint32_t off = (uint32_t)(p * 16 + bRow) * AROWB + kc * 32 + bByte;
                uint32_t th[4];
                ldm4(th, kb + off);
                mma16816(S[2 * p],     qf[kc], th);
                mma16816(S[2 * p + 1], qf[kc], th + 2);
            }
        }

        int qr0 = q0 + wm * 16 + g;
        bool needMask = causal && (l0 + 63 > q0 + wm * 16);
        #pragma unroll
        for (int j = 0; j < 8; j++) {
            int lg = l0 + j * 8 + 2 * qd;
            #pragma unroll
            for (int c = 0; c < 4; c++) {
                float v = S[j][c] * scale;
                if (needMask) {
                    int lq = lg + (c & 1);
                    int qq = qr0 + (c >> 1) * 8;
                    if (lq > qq) v = -1e30f;
                }
                S[j][c] = v;
            }
        }

        float alpha[2];
        #pragma unroll
        for (int hfi = 0; hfi < 2; hfi++) {
            float tm = -1e30f;
            #pragma unroll
            for (int j = 0; j < 8; j++) {
                tm = fmaxf(tm, S[j][2 * hfi]);
                tm = fmaxf(tm, S[j][2 * hfi + 1]);
            }
            tm = fmaxf(tm, __shfl_xor_sync(0xffffffffu, tm, 1));
            tm = fmaxf(tm, __shfl_xor_sync(0xffffffffu, tm, 2));
            float mnew = fmaxf(mrow[hfi], tm);
            alpha[hfi] = __expf(mrow[hfi] - mnew);
            mrow[hfi] = mnew;
            float rs = 0.f;
            #pragma unroll
            for (int j = 0; j < 8; j++) {
                float e0 = __expf(S[j][2 * hfi] - mnew);
                float e1 = __expf(S[j][2 * hfi + 1] - mnew);
                S[j][2 * hfi] = e0; S[j][2 * hfi + 1] = e1;
                rs += e0 + e1;
            }
            rs += __shfl_xor_sync(0xffffffffu, rs, 1);
            rs += __shfl_xor_sync(0xffffffffu, rs, 2);
            lrow[hfi] = lrow[hfi] * alpha[hfi] + rs;
        }
        #pragma unroll
        for (int j = 0; j < 8; j++) {
            Oacc[j][0] *= alpha[0]; Oacc[j][1] *= alpha[0];
            Oacc[j][2] *= alpha[1]; Oacc[j][3] *= alpha[1];
        }

        uint32_t vb = kb + AKV_BYTES;
        #pragma unroll
        for (int kc = 0; kc < 4; kc++) {
            uint32_t ph[4];
            #pragma unroll
            for (int r = 0; r < 2; r++) {
                int j = 2 * kc + r;
                ph[2 * r]     = packhf(S[j][0], S[j][1]);
                ph[2 * r + 1] = packhf(S[j][2], S[j][3]);
            }
            #pragma unroll
            for (int p = 0; p < 4; p++) {
                uint32_t off = (uint32_t)(kc * 16 + vRow) * AROWB + p * 32 + vByte;
                uint32_t tvh[4];
                ldm4t(tvh, vb + off);
                mma16816(Oacc[2 * p],     ph, tvh);
                mma16816(Oacc[2 * p + 1], ph, tvh + 2);
            }
        }
        __syncthreads();
    }

    float inv0 = 1.f / lrow[0], inv1 = 1.f / lrow[1];
    #pragma unroll
    for (int j = 0; j < 8; j++) {
        int d = j * 8 + 2 * qd;
        size_t base0 = ((size_t)n * Kk + q0 + wm * 16 + g) * Mm + (size_t)h * Dd + d;
        size_t base1 = base0 + (size_t)8 * Mm;
        *(uint32_t*)(O + base0) = packhf(Oacc[j][0] * inv0, Oacc[j][1] * inv0);
        *(uint32_t*)(O + base1) = packhf(Oacc[j][2] * inv1, Oacc[j][3] * inv1);
    }
}

// ---------------- fused prep (unchanged) ----------------
#define PREP_GRID 12293

__global__ __launch_bounds__(256) void prep_all(
    const float* __restrict__ dec, const float* __restrict__ enc,
    const float* __restrict__ Wq_s, const float* __restrict__ Wk_s, const float* __restrict__ Wv_s,
    const float* __restrict__ Wq_c, const float* __restrict__ Wk_c, const float* __restrict__ Wv_c,
    const float* __restrict__ Wo_s, const float* __restrict__ Wo_c,
    const float* __restrict__ W1, const float* __restrict__ W2,
    const float* __restrict__ bq_s, const float* __restrict__ bk_s, const float* __restrict__ bv_s,
    const float* __restrict__ bk_c, const float* __restrict__ bv_c,
    hf* __restrict__ w16, hf* __restrict__ d16, hf* __restrict__ e16,
    float* __restrict__ b3, float* __restrict__ b2c)
{
    int b = blockIdx.x;
    int tid = threadIdx.x;

    if (b < 8192) {
        __shared__ float t[32][65];
        const float* src; hf* dst;
        int R, C, z = 0, tile;
        size_t inZ = 0, outZ = 0;
        if (b < 3072) {
            int w = b >> 9; tile = b & 511;
            const float* ws[6] = {Wq_s, Wk_s, Wv_s, Wq_c, Wk_c, Wv_c};
            src = ws[w]; dst = w16 + (size_t)w * 1048576;
            R = 1024; C = 64; inZ = 65536; outZ = 65536;
            z = tile >> 5; tile &= 31;
        } else if (b < 4096) {
            int w = (b - 3072) >> 9; tile = (b - 3072) & 511;
            src = w ? Wo_c : Wo_s; dst = w16 + (size_t)(6 + w) * 1048576;
            R = 1024; C = 1024;
        } else if (b < 6144) {
            tile = b - 4096;
            src = W1; dst = w16 + (size_t)WOFF_W1;
            R = 1024; C = 4096;
        } else {
            tile = b - 6144;
            src = W2; dst = w16 + (size_t)WOFF_W2;
            R = 4096; C = 1024;
        }
        int cTiles = C >> 5;
        int rt = tile / cTiles, ct = tile - rt * cTiles;
        int r0 = rt << 6, c0 = ct << 5;
        const float* ip = src + (size_t)z * inZ;
        hf* op = dst + (size_t)z * outZ;

        int tx = tid & 31, ty = tid >> 5;
        #pragma unroll
        for (int i = 0; i < 8; i++) {
            int row = ty + i * 8;
            t[tx][row] = ip[(size_t)(r0 + row) * C + c0 + tx];
        }
        __syncthreads();
        #pragma unroll
        for (int i = 0; i < 4; i++) {
            int cc = ty + i * 8;
            float v0 = t[cc][2 * tx];
            float v1 = t[cc][2 * tx + 1];
            size_t o = (size_t)(c0 + cc) * R + r0 + 2 * tx;
            *(uint32_t*)(op + o) = packhf(v0, v1);
        }
    } else if (b < 12288) {
        const float* src = (b < 10240) ? dec : enc;
        hf* dst = (b < 10240) ? d16 : e16;
        int blk = (b < 10240) ? (b - 8192) : (b - 10240);
        size_t i = ((size_t)blk * 256 + tid) * 8;
        float4 v0 = *(const float4*)(src + i);
        float4 v1 = *(const float4*)(src + i + 4);
        *(uint32_t*)(dst + i)     = packhf(v0.x, v0.y);
        *(uint32_t*)(dst + i + 2) = packhf(v0.z, v0.w);
        *(uint32_t*)(dst + i + 4) = packhf(v1.x, v1.y);
        *(uint32_t*)(dst + i + 6) = packhf(v1.z, v1.w);
    } else if (b < 12291) {
        int i = (b - 12288) * 1024 + tid * 4;
        #pragma unroll
        for (int c = 0; c < 4; c++) {
            int j = i + c;
            b3[j] = (j < 1024) ? bq_s[j] : ((j < 2048) ? bk_s[j - 1024] : bv_s[j - 2048]);
        }
    } else {
        int i = (b - 12291) * 1024 + tid * 4;
        #pragma unroll
        for (int c = 0; c < 4; c++) {
            int j = i + c;
            b2c[j] = (j < 1024) ? bk_c[j] : bv_c[j - 1024];
        }
    }
}

// ---------------- LayerNorm (block per row, M=1024), optional fp16 out ----------------
__global__ void ln_kernel(const float* __restrict__ X, const float* __restrict__ g,
                          const float* __restrict__ b, float* __restrict__ Y,
                          hf* __restrict__ Yh)
{
    int row = blockIdx.x;
    int tid = threadIdx.x;
    const float* x = X + (size_t)row * Mm;
    float4 v = *(const float4*)(x + tid * 4);

    __shared__ float red[256];
    red[tid] = v.x + v.y + v.z + v.w;
    __syncthreads();
    for (int o = 128; o > 0; o >>= 1) {
        if (tid < o) red[tid] += red[tid + o];
        __syncthreads();
    }
    float mu = red[0] * (1.f / 1024.f);
    __syncthreads();

    float d0 = v.x - mu, d1 = v.y - mu, d2 = v.z - mu, d3 = v.w - mu;
    red[tid] = d0 * d0 + d1 * d1 + d2 * d2 + d3 * d3;
    __syncthreads();
    for (int o = 128; o > 0; o >>= 1) {
        if (tid < o) red[tid] += red[tid + o];
        __syncthreads();
    }
    float inv = rsqrtf(red[0] * (1.f / 1024.f) + 1e-5f);

    float4 gg = *(const float4*)(g + tid * 4);
    float4 bb = *(const float4*)(b + tid * 4);
    float y0 = d0 * inv * gg.x + bb.x;
    float y1 = d1 * inv * gg.y + bb.y;
    float y2 = d2 * inv * gg.z + bb.z;
    float y3 = d3 * inv * gg.w + bb.w;
    float4 yv = {y0, y1, y2, y3};
    *(float4*)(Y + (size_t)row * Mm + tid * 4) = yv;
    if (Yh) {
        size_t base = (size_t)row * Mm + tid * 4;
        *(uint32_t*)(Yh + base)     = packhf(y0, y1);
        *(uint32_t*)(Yh + base + 2) = packhf(y2, y3);
    }
}

// ---------------- host ----------------
static void launch_gemm(const hf* A, const hf* B,
                        const float* bias, const float* res,
                        float* Cf, hf* Ch,
                        int I, int Kd, int J, int relu)
{
    dim3 grid(J / 128, I / 128);
    gemm_tc<<<grid, 256, GSM_SIZE>>>(A, B, bias, res, Cf, Ch, Kd, J, relu);
}

extern "C" void kernel_launch(void* const* d_in, const int* in_sizes, int n_in,
                              void* d_out, int out_size)
{
    const float* dec  = (const float*)d_in[0];
    const float* enc  = (const float*)d_in[1];
    const float* Wq_s = (const float*)d_in[3];  const float* bq_s = (const float*)d_in[4];
    const float* Wk_s = (const float*)d_in[5];  const float* bk_s = (const float*)d_in[6];
    const float* Wv_s = (const float*)d_in[7];  const float* bv_s = (const float*)d_in[8];
    const float* Wo_s = (const float*)d_in[9];  const float* bo_s = (const float*)d_in[10];
    const float* Wq_c = (const float*)d_in[11]; const float* bq_c = (const float*)d_in[12];
    const float* Wk_c = (const float*)d_in[13]; const float* bk_c = (const float*)d_in[14];
    const float* Wv_c = (const float*)d_in[15]; const float* bv_c = (const float*)d_in[16];
    const float* Wo_c = (const float*)d_in[17]; const float* bo_c = (const float*)d_in[18];
    const float* W1   = (const float*)d_in[19]; const float* b1   = (const float*)d_in[20];
    const float* W2   = (const float*)d_in[21]; const float* b2   = (const float*)d_in[22];
    const float* g1   = (const float*)d_in[23]; const float* be1  = (const float*)d_in[24];
    const float* g2   = (const float*)d_in[25]; const float* be2  = (const float*)d_in[26];
    const float* g3   = (const float*)d_in[27]; const float* be3  = (const float*)d_in[28];
    float* out = (float*)d_out;

    cudaFuncSetAttribute(gemm_tc, cudaFuncAttributeMaxDynamicSharedMemorySize, GSM_SIZE);
    cudaFuncSetAttribute(attn_tc, cudaFuncAttributeMaxDynamicSharedMemorySize, ATTN_SMEM2);

    float *x, *y, *z, *b3, *b2c;
    hf *d16, *e16, *yh, *zh, *a16, *h16, *w16, *qkv, *kv, *q16;
    cudaGetSymbolAddress((void**)&x, g_x);
    cudaGetSymbolAddress((void**)&y, g_y);   cudaGetSymbolAddress((void**)&z, g_z);
    cudaGetSymbolAddress((void**)&b3, g_b3); cudaGetSymbolAddress((void**)&b2c, g_b2);
    cudaGetSymbolAddress((void**)&d16, g_d); cudaGetSymbolAddress((void**)&e16, g_e);
    cudaGetSymbolAddress((void**)&yh, g_yh); cudaGetSymbolAddress((void**)&zh, g_zh);
    cudaGetSymbolAddress((void**)&a16, g_a); cudaGetSymbolAddress((void**)&h16, g_h);
    cudaGetSymbolAddress((void**)&w16, g_w);
    cudaGetSymbolAddress((void**)&qkv, g_qkv);
    cudaGetSymbolAddress((void**)&kv, g_kv);
    cudaGetSymbolAddress((void**)&q16, g_q);

    // ---- fused prep ----
    prep_all<<<PREP_GRID, 256>>>(dec, enc,
                                 Wq_s, Wk_s, Wv_s, Wq_c, Wk_c, Wv_c,
                                 Wo_s, Wo_c, W1, W2,
                                 bq_s, bk_s, bv_s, bk_c, bv_c,
                                 w16, d16, e16, b3, b2c);

    dim3 agrid(Kk / 128, Nn * Hh);

    // ---- self attention (fused QKV: J=3072) ----
    launch_gemm(d16, w16 + WOFF_QS, b3, nullptr, nullptr, qkv, NK, Mm, 3 * Mm, 0);
    attn_tc<<<agrid, 256, ATTN_SMEM2>>>(qkv, qkv + 1024, qkv + 2048, 3072, 3072, 1, a16);
    launch_gemm(a16, w16 + WOFF_OS, bo_s, dec, x, nullptr, NK, Mm, Mm, 0);
    ln_kernel<<<NK, 256>>>(x, g1, be1, y, yh);

    // ---- cross attention (fused KV: J=2048) ----
    launch_gemm(yh, w16 + WOFF_QC, bq_c, nullptr, nullptr, q16, NK, Mm, Mm, 0);
    launch_gemm(e16, w16 + WOFF_KC, b2c, nullptr, nullptr, kv, NK, Mm, 2 * Mm, 0);
    attn_tc<<<agrid, 256, ATTN_SMEM2>>>(q16, kv, kv + 1024, 1024, 2048, 0, a16);
    launch_gemm(a16, w16 + WOFF_OC, bo_c, y, x, nullptr, NK, Mm, Mm, 0);
    ln_kernel<<<NK, 256>>>(x, g2, be2, z, zh);

    // ---- feedforward ----
    launch_gemm(zh, w16 + WOFF_W1, b1, nullptr, nullptr, h16, NK, Mm, Ff, 1);
    launch_gemm(h16, w16 + WOFF_W2, b2, z, x, nullptr, NK, Ff, Mm, 0);
    ln_kernel<<<NK, 256>>>(x, g3, be3, out, nullptr);
}